// round 1
// baseline (speedup 1.0000x reference)
#include <cuda_runtime.h>

#define Bn 128
#define Nn 256
#define Dn 512
#define Hn 1024
#define Ln 3

// Scratch (static device arrays — no allocation at kernel_launch time)
__device__ float g_x [(size_t)Bn * Nn * Dn];   //  64 MB ping buffer for x
__device__ float g_nb[(size_t)Bn * Nn * Dn];   //  64 MB neighbor aggregate
__device__ float g_h [(size_t)Bn * Nn * Hn];   // 128 MB hidden activations
__device__ float g_adj[Nn * Nn];               // softmax-normalized adjacency

// ---------------------------------------------------------------------------
// Row softmax over adjacency [N, N]. One block (256 threads) per row.
// Writes both the scratch copy (used by GEMMs) and the output slice.
// ---------------------------------------------------------------------------
__global__ void softmax_rows(const float* __restrict__ adj,
                             float* __restrict__ out1,
                             float* __restrict__ out2)
{
    int row = blockIdx.x;
    int t   = threadIdx.x;
    float v = adj[row * Nn + t];

    __shared__ float red[8];

    // block max
    float m = v;
    #pragma unroll
    for (int o = 16; o > 0; o >>= 1)
        m = fmaxf(m, __shfl_xor_sync(0xffffffffu, m, o));
    if ((t & 31) == 0) red[t >> 5] = m;
    __syncthreads();
    m = red[0];
    #pragma unroll
    for (int i = 1; i < 8; i++) m = fmaxf(m, red[i]);
    __syncthreads();

    float e = expf(v - m);

    // block sum
    float s = e;
    #pragma unroll
    for (int o = 16; o > 0; o >>= 1)
        s += __shfl_xor_sync(0xffffffffu, s, o);
    if ((t & 31) == 0) red[t >> 5] = s;
    __syncthreads();
    s = red[0];
    #pragma unroll
    for (int i = 1; i < 8; i++) s += red[i];

    float o = e / s;
    out1[row * Nn + t] = o;
    out2[row * Nn + t] = o;
}

// ---------------------------------------------------------------------------
// C[m][n] = act( sum_k A[m][k] * Bt[n][k] + bias[n] )  (+ resid[m][n])
// A: [M,K] row-major (K contiguous), Bt: [Ncol,K] row-major (K contiguous).
// Tile 128x128x16, 256 threads, 8x8 per thread.
// ---------------------------------------------------------------------------
template<bool RELU, bool RESID>
__global__ __launch_bounds__(256)
void gemm_abt(const float* __restrict__ A, const float* __restrict__ Bt,
              const float* __restrict__ bias, const float* __restrict__ resid,
              float* __restrict__ C, int M, int Ncol, int K)
{
    __shared__ float As[16][128];
    __shared__ float Bs[16][128];

    int bm  = blockIdx.y * 128;
    int bn  = blockIdx.x * 128;
    int tid = threadIdx.x;
    int tx  = tid & 15;
    int ty  = tid >> 4;

    const float* Ap = A  + (size_t)bm * K;
    const float* Bp = Bt + (size_t)bn * K;

    float acc[8][8];
    #pragma unroll
    for (int i = 0; i < 8; i++)
        #pragma unroll
        for (int j = 0; j < 8; j++) acc[i][j] = 0.f;

    for (int k0 = 0; k0 < K; k0 += 16) {
        #pragma unroll
        for (int i = 0; i < 2; i++) {
            int f = tid + i * 256;          // 512 float4 loads per operand tile
            int r = f >> 2;                  // row within 128-row tile
            int c = (f & 3) << 2;            // k offset within 16
            float4 va = *(const float4*)(Ap + (size_t)r * K + k0 + c);
            As[c + 0][r] = va.x; As[c + 1][r] = va.y;
            As[c + 2][r] = va.z; As[c + 3][r] = va.w;
            float4 vb = *(const float4*)(Bp + (size_t)r * K + k0 + c);
            Bs[c + 0][r] = vb.x; Bs[c + 1][r] = vb.y;
            Bs[c + 2][r] = vb.z; Bs[c + 3][r] = vb.w;
        }
        __syncthreads();

        #pragma unroll
        for (int k = 0; k < 16; k++) {
            float a[8], b[8];
            *(float4*)&a[0] = *(const float4*)&As[k][ty * 8];
            *(float4*)&a[4] = *(const float4*)&As[k][ty * 8 + 4];
            *(float4*)&b[0] = *(const float4*)&Bs[k][tx * 8];
            *(float4*)&b[4] = *(const float4*)&Bs[k][tx * 8 + 4];
            #pragma unroll
            for (int i = 0; i < 8; i++)
                #pragma unroll
                for (int j = 0; j < 8; j++)
                    acc[i][j] = fmaf(a[i], b[j], acc[i][j]);
        }
        __syncthreads();
    }

    float bv[8];
    #pragma unroll
    for (int j = 0; j < 8; j++) bv[j] = bias[bn + tx * 8 + j];

    #pragma unroll
    for (int i = 0; i < 8; i++) {
        size_t rowoff = (size_t)(bm + ty * 8 + i) * Ncol + bn + tx * 8;
        #pragma unroll
        for (int j = 0; j < 8; j++) {
            float v = acc[i][j] + bv[j];
            if (RELU)  v = fmaxf(v, 0.f);
            if (RESID) v += resid[rowoff + j];
            C[rowoff + j] = v;
        }
    }
}

// ---------------------------------------------------------------------------
// Batched neighbor aggregation: C[b] = Aadj[256,256] @ X[b][256,512]
// Aadj K-contiguous, X N-contiguous. Tile 128x128x16.
// ---------------------------------------------------------------------------
__global__ __launch_bounds__(256)
void gemm_adj(const float* __restrict__ Aadj, const float* __restrict__ X,
              float* __restrict__ C)
{
    __shared__ float As[16][128];
    __shared__ float Bs[16][128];

    int bm = blockIdx.y * 128;   // c
    int bn = blockIdx.x * 128;   // d
    int bz = blockIdx.z;         // batch
    const float* Xb = X + (size_t)bz * Nn * Dn;
    float*       Cb = C + (size_t)bz * Nn * Dn;

    int tid = threadIdx.x;
    int tx  = tid & 15;
    int ty  = tid >> 4;

    float acc[8][8];
    #pragma unroll
    for (int i = 0; i < 8; i++)
        #pragma unroll
        for (int j = 0; j < 8; j++) acc[i][j] = 0.f;

    for (int k0 = 0; k0 < Nn; k0 += 16) {
        #pragma unroll
        for (int i = 0; i < 2; i++) {
            int f = tid + i * 256;
            // A tile: 128 rows (c) x 16 k, K-contiguous -> store transposed
            int r = f >> 2;
            int c = (f & 3) << 2;
            float4 va = *(const float4*)(Aadj + (size_t)(bm + r) * Nn + k0 + c);
            As[c + 0][r] = va.x; As[c + 1][r] = va.y;
            As[c + 2][r] = va.z; As[c + 3][r] = va.w;
            // B tile: 16 rows (k) x 128 cols (d), d-contiguous -> direct
            int rb = f >> 5;
            int cb = (f & 31) << 2;
            *(float4*)&Bs[rb][cb] =
                *(const float4*)(Xb + (size_t)(k0 + rb) * Dn + bn + cb);
        }
        __syncthreads();

        #pragma unroll
        for (int k = 0; k < 16; k++) {
            float a[8], b[8];
            *(float4*)&a[0] = *(const float4*)&As[k][ty * 8];
            *(float4*)&a[4] = *(const float4*)&As[k][ty * 8 + 4];
            *(float4*)&b[0] = *(const float4*)&Bs[k][tx * 8];
            *(float4*)&b[4] = *(const float4*)&Bs[k][tx * 8 + 4];
            #pragma unroll
            for (int i = 0; i < 8; i++)
                #pragma unroll
                for (int j = 0; j < 8; j++)
                    acc[i][j] = fmaf(a[i], b[j], acc[i][j]);
        }
        __syncthreads();
    }

    #pragma unroll
    for (int i = 0; i < 8; i++) {
        size_t rowoff = (size_t)(bm + ty * 8 + i) * Dn + bn + tx * 8;
        #pragma unroll
        for (int j = 0; j < 8; j++)
            Cb[rowoff + j] = acc[i][j];
    }
}

// ---------------------------------------------------------------------------
// pooled[b][d] = mean_n x[b][n][d]
// ---------------------------------------------------------------------------
__global__ void pool_mean(const float* __restrict__ x, float* __restrict__ pooled)
{
    int idx = blockIdx.x * blockDim.x + threadIdx.x;   // b*Dn + d
    int b = idx / Dn;
    int d = idx - b * Dn;
    const float* p = x + (size_t)b * Nn * Dn + d;
    float s = 0.f;
    #pragma unroll 8
    for (int n = 0; n < Nn; n++) s += p[(size_t)n * Dn];
    pooled[idx] = s * (1.f / Nn);
}

// ---------------------------------------------------------------------------
extern "C" void kernel_launch(void* const* d_in, const int* in_sizes, int n_in,
                              void* d_out, int out_size)
{
    const float* x0  = (const float*)d_in[0];   // [B,N,D]
    const float* adj = (const float*)d_in[1];   // [N,N]
    const float* W1  = (const float*)d_in[2];   // [L,H,D]
    const float* b1  = (const float*)d_in[3];   // [L,H]
    const float* W2  = (const float*)d_in[4];   // [L,D,H]
    const float* b2  = (const float*)d_in[5];   // [L,D]

    float* out      = (float*)d_out;
    float* out_x    = out;                                   // [B,N,D]
    float* out_pool = out + (size_t)Bn * Nn * Dn;            // [B,D]
    float* out_adj  = out_pool + (size_t)Bn * Dn;            // [N,N]

    float *gx, *gnb, *gh, *gadj;
    cudaGetSymbolAddress((void**)&gx,   g_x);
    cudaGetSymbolAddress((void**)&gnb,  g_nb);
    cudaGetSymbolAddress((void**)&gh,   g_h);
    cudaGetSymbolAddress((void**)&gadj, g_adj);

    softmax_rows<<<Nn, Nn>>>(adj, gadj, out_adj);

    const float* xin = x0;
    for (int i = 0; i < Ln; i++) {
        float* xout = (i == Ln - 1) ? out_x : gx;

        // neighbor = adj_norm @ x   (batched over B)
        gemm_adj<<<dim3(Dn / 128, Nn / 128, Bn), 256>>>(gadj, xin, gnb);

        // h = relu(neighbor @ W1^T + b1)
        gemm_abt<true, false><<<dim3(Hn / 128, (Bn * Nn) / 128), 256>>>(
            gnb, W1 + (size_t)i * Hn * Dn, b1 + (size_t)i * Hn,
            nullptr, gh, Bn * Nn, Hn, Dn);

        // x = x + h @ W2^T + b2
        gemm_abt<false, true><<<dim3(Dn / 128, (Bn * Nn) / 128), 256>>>(
            gh, W2 + (size_t)i * Dn * Hn, b2 + (size_t)i * Dn,
            xin, xout, Bn * Nn, Dn, Hn);

        xin = xout;
    }

    pool_mean<<<(Bn * Dn) / 256, 256>>>(out_x, out_pool);
}

// round 3
// speedup vs baseline: 2.5112x; 2.5112x over previous
#include <cuda_runtime.h>
#include <cuda_bf16.h>
#include <cstdint>

#define Bn 128
#define Nn 256
#define Dn 512
#define Hn 1024
#define Ln 3

// ---------------------------------------------------------------------------
// Scratch planes (static device arrays; 16B-aligned for uint4 access)
// ---------------------------------------------------------------------------
__device__ __align__(256) __nv_bfloat16 g_adjh[Nn * Nn];
__device__ __align__(256) __nv_bfloat16 g_adjl[Nn * Nn];
__device__ __align__(256) __nv_bfloat16 g_xh [(size_t)Bn * Nn * Dn];
__device__ __align__(256) __nv_bfloat16 g_xl [(size_t)Bn * Nn * Dn];
__device__ __align__(256) __nv_bfloat16 g_nbh[(size_t)Bn * Nn * Dn];
__device__ __align__(256) __nv_bfloat16 g_nbl[(size_t)Bn * Nn * Dn];
__device__ __align__(256) __nv_bfloat16 g_hh [(size_t)Bn * Nn * Hn];
__device__ __align__(256) __nv_bfloat16 g_hl [(size_t)Bn * Nn * Hn];
__device__ __align__(256) __nv_bfloat16 g_w1h[(size_t)Ln * Hn * Dn];
__device__ __align__(256) __nv_bfloat16 g_w1l[(size_t)Ln * Hn * Dn];
__device__ __align__(256) __nv_bfloat16 g_w2h[(size_t)Ln * Dn * Hn];
__device__ __align__(256) __nv_bfloat16 g_w2l[(size_t)Ln * Dn * Hn];
__device__ __align__(256) float         g_x  [(size_t)Bn * Nn * Dn];

// ---------------------------------------------------------------------------
// warp-mma helpers (sm_80-level PTX: works at compute_103 target)
// ---------------------------------------------------------------------------
__device__ __forceinline__ uint32_t smem_u32(const void* p) {
    uint32_t a;
    asm("{ .reg .u64 t; cvta.to.shared.u64 t, %1; cvt.u32.u64 %0, t; }"
        : "=r"(a) : "l"(p));
    return a;
}

__device__ __forceinline__ void ldsm_x4(uint32_t (&r)[4], uint32_t addr) {
    asm volatile("ldmatrix.sync.aligned.m8n8.x4.shared.b16 {%0,%1,%2,%3}, [%4];"
        : "=r"(r[0]), "=r"(r[1]), "=r"(r[2]), "=r"(r[3]) : "r"(addr));
}
__device__ __forceinline__ void ldsm_x4_t(uint32_t (&r)[4], uint32_t addr) {
    asm volatile("ldmatrix.sync.aligned.m8n8.x4.trans.shared.b16 {%0,%1,%2,%3}, [%4];"
        : "=r"(r[0]), "=r"(r[1]), "=r"(r[2]), "=r"(r[3]) : "r"(addr));
}
__device__ __forceinline__ void mma16816(float (&d)[4], const uint32_t (&a)[4],
                                         uint32_t b0, uint32_t b1) {
    asm volatile(
        "mma.sync.aligned.m16n8k16.row.col.f32.bf16.bf16.f32 "
        "{%0,%1,%2,%3}, {%4,%5,%6,%7}, {%8,%9}, {%0,%1,%2,%3};"
        : "+f"(d[0]), "+f"(d[1]), "+f"(d[2]), "+f"(d[3])
        : "r"(a[0]), "r"(a[1]), "r"(a[2]), "r"(a[3]), "r"(b0), "r"(b1));
}

__device__ __forceinline__ void split_bf16(float v, uint16_t& h, uint16_t& l) {
    __nv_bfloat16 hb = __float2bfloat16(v);
    float hf = __bfloat162float(hb);
    __nv_bfloat16 lb = __float2bfloat16(v - hf);
    h = __bfloat16_as_ushort(hb);
    l = __bfloat16_as_ushort(lb);
}

// ---------------------------------------------------------------------------
// Row softmax over adjacency [N,N]: fp32 output + bf16 hi/lo planes
// ---------------------------------------------------------------------------
__global__ void softmax_rows(const float* __restrict__ adj,
                             float* __restrict__ out_adj,
                             __nv_bfloat16* __restrict__ hi,
                             __nv_bfloat16* __restrict__ lo)
{
    int row = blockIdx.x;
    int t   = threadIdx.x;
    float v = adj[row * Nn + t];

    __shared__ float red[8];
    float m = v;
    #pragma unroll
    for (int o = 16; o > 0; o >>= 1)
        m = fmaxf(m, __shfl_xor_sync(0xffffffffu, m, o));
    if ((t & 31) == 0) red[t >> 5] = m;
    __syncthreads();
    m = red[0];
    #pragma unroll
    for (int i = 1; i < 8; i++) m = fmaxf(m, red[i]);
    __syncthreads();

    float e = expf(v - m);
    float s = e;
    #pragma unroll
    for (int o = 16; o > 0; o >>= 1)
        s += __shfl_xor_sync(0xffffffffu, s, o);
    if ((t & 31) == 0) red[t >> 5] = s;
    __syncthreads();
    s = red[0];
    #pragma unroll
    for (int i = 1; i < 8; i++) s += red[i];

    float o = e / s;
    out_adj[row * Nn + t] = o;
    uint16_t h, l;
    split_bf16(o, h, l);
    hi[row * Nn + t] = __ushort_as_bfloat16(h);
    lo[row * Nn + t] = __ushort_as_bfloat16(l);
}

// ---------------------------------------------------------------------------
// fp32 -> (bf16 hi, bf16 lo) planes, vectorized by 4
// ---------------------------------------------------------------------------
__global__ void split_convert(const float* __restrict__ in,
                              __nv_bfloat16* __restrict__ hi,
                              __nv_bfloat16* __restrict__ lo, int n4)
{
    int idx = blockIdx.x * blockDim.x + threadIdx.x;
    if (idx >= n4) return;
    float4 v = ((const float4*)in)[idx];
    float a[4] = {v.x, v.y, v.z, v.w};
    uint16_t h[4], l[4];
    #pragma unroll
    for (int e = 0; e < 4; e++) split_bf16(a[e], h[e], l[e]);
    ((uint2*)hi)[idx] = make_uint2((uint32_t)h[0] | ((uint32_t)h[1] << 16),
                                   (uint32_t)h[2] | ((uint32_t)h[3] << 16));
    ((uint2*)lo)[idx] = make_uint2((uint32_t)l[0] | ((uint32_t)l[1] << 16),
                                   (uint32_t)l[2] | ((uint32_t)l[3] << 16));
}

// ---------------------------------------------------------------------------
// mma.sync GEMM: C[M,Ncol] = act(A @ op(B) + bias) (+resid)
//   A: hi/lo bf16 planes, [M,K] row-major (m x k)
//   B NT case: hi/lo planes [Ncol,K] row-major (weights; natively B col-major)
//   B T  case: hi/lo planes [K,Ncol] row-major (x; batched via blockIdx.z)
// CTA tile 128x128x32, 8 warps (2x4), warp tile 64x32.
// ---------------------------------------------------------------------------
#define PITCH_A  40      // halves; 80B = 5*16 (keeps 16B alignment per row)
#define PITCH_BT 136     // halves; 272B = 17*16
#define SPLIT_SZ 5120    // halves per split plane in smem

template<bool TRANSB, bool HASBIAS, bool RELU, bool RESID, bool OUTF32, bool OUTPLANES>
__global__ void __launch_bounds__(256, 2)
mma_gemm(const __nv_bfloat16* __restrict__ Ah, const __nv_bfloat16* __restrict__ Al,
         const __nv_bfloat16* __restrict__ Bh, const __nv_bfloat16* __restrict__ Bl,
         const float* __restrict__ bias, const float* __restrict__ resid,
         float* __restrict__ Cf,
         __nv_bfloat16* __restrict__ Ch, __nv_bfloat16* __restrict__ Cl,
         int Ncol, int K)
{
    __shared__ __align__(16) __nv_bfloat16 sA[2 * SPLIT_SZ];
    __shared__ __align__(16) __nv_bfloat16 sB[2 * SPLIT_SZ];
    __shared__ float sbias[128];

    const int tid  = threadIdx.x;
    const int lane = tid & 31;
    const int wid  = tid >> 5;
    const int mwarp = (wid >> 2) * 64;   // 0 or 64
    const int nwarp = (wid & 3) * 32;    // 0,32,64,96
    const int bm = blockIdx.y * 128;
    const int bn = blockIdx.x * 128;
    const int z  = blockIdx.z;

    size_t arow0 = TRANSB ? (size_t)bm : ((size_t)bm);           // A row base (adj: bm)
    const __nv_bfloat16* Bhp = Bh;
    const __nv_bfloat16* Blp = Bl;
    size_t out_row0;
    if (TRANSB) {
        Bhp = Bh + (size_t)z * Nn * Dn;
        Blp = Bl + (size_t)z * Nn * Dn;
        out_row0 = (size_t)z * Nn + bm;
    } else {
        out_row0 = (size_t)bm;
    }

    if (HASBIAS && tid < 128) sbias[tid] = bias[bn + tid];

    float acc[4][4][4];
    #pragma unroll
    for (int mi = 0; mi < 4; mi++)
        #pragma unroll
        for (int ni = 0; ni < 4; ni++)
            #pragma unroll
            for (int e = 0; e < 4; e++) acc[mi][ni][e] = 0.f;

    // per-thread ldmatrix base addresses
    const int q = lane >> 3, li = lane & 7;
    const uint32_t sA_u = smem_u32(sA);
    const uint32_t sB_u = smem_u32(sB);
    // A frag: mat rows = (q&1)*8 + li, mat col block = (q>>1)*8
    const uint32_t aBase = sA_u + (uint32_t)(((mwarp + (q & 1) * 8 + li) * PITCH_A
                                             + (q >> 1) * 8) << 1);
    uint32_t bBase;
    if (TRANSB) // B smem [k=32][n=128+8]; trans ldmatrix; rows = k, col = n
        bBase = sB_u + (uint32_t)((((q & 1) * 8 + li) * PITCH_BT
                                  + nwarp + (q >> 1) * 8) << 1);
    else        // B smem [n=128][k=32+8]; non-trans; rows = n, col = k
        bBase = sB_u + (uint32_t)(((nwarp + (q >> 1) * 8 + li) * PITCH_A
                                  + (q & 1) * 8) << 1);

    for (int k0 = 0; k0 < K; k0 += 32) {
        // ---- load A tile (both splits): 128 x 32 halves each ----
        #pragma unroll
        for (int it = 0; it < 2; it++) {
            int f = tid + it * 256;
            int r = f >> 2, c = (f & 3) << 3;
            size_t g = (arow0 + r) * (size_t)K + k0 + c;
            *(uint4*)&sA[r * PITCH_A + c]            = *(const uint4*)(Ah + g);
            *(uint4*)&sA[SPLIT_SZ + r * PITCH_A + c] = *(const uint4*)(Al + g);
        }
        // ---- load B tile ----
        if (TRANSB) {
            #pragma unroll
            for (int it = 0; it < 2; it++) {
                int f = tid + it * 256;
                int r = f >> 4, c = (f & 15) << 3;   // r: k 0..31, c: n 0..127
                size_t g = (size_t)(k0 + r) * Ncol + bn + c;
                *(uint4*)&sB[r * PITCH_BT + c]            = *(const uint4*)(Bhp + g);
                *(uint4*)&sB[SPLIT_SZ + r * PITCH_BT + c] = *(const uint4*)(Blp + g);
            }
        } else {
            #pragma unroll
            for (int it = 0; it < 2; it++) {
                int f = tid + it * 256;
                int r = f >> 2, c = (f & 3) << 3;    // r: n 0..127, c: k 0..31
                size_t g = (size_t)(bn + r) * K + k0 + c;
                *(uint4*)&sB[r * PITCH_A + c]            = *(const uint4*)(Bhp + g);
                *(uint4*)&sB[SPLIT_SZ + r * PITCH_A + c] = *(const uint4*)(Blp + g);
            }
        }
        __syncthreads();

        #pragma unroll
        for (int ks = 0; ks < 2; ks++) {
            // B fragments, both splits: [split][nj][4]
            uint32_t bh[2][4], bl[2][4];
            #pragma unroll
            for (int nj = 0; nj < 2; nj++) {
                if (TRANSB) {
                    uint32_t o = (uint32_t)((ks * 16 * PITCH_BT + nj * 16) << 1);
                    ldsm_x4_t(bh[nj], bBase + o);
                    ldsm_x4_t(bl[nj], bBase + (uint32_t)(SPLIT_SZ << 1) + o);
                } else {
                    uint32_t o = (uint32_t)((nj * 16 * PITCH_A + ks * 16) << 1);
                    ldsm_x4(bh[nj], bBase + o);
                    ldsm_x4(bl[nj], bBase + (uint32_t)(SPLIT_SZ << 1) + o);
                }
            }
            uint32_t af[4][4];
            // A-hi frags, then hh + hl MMAs
            #pragma unroll
            for (int mi = 0; mi < 4; mi++)
                ldsm_x4(af[mi], aBase + (uint32_t)((mi * 16 * PITCH_A + ks * 16) << 1));
            #pragma unroll
            for (int mi = 0; mi < 4; mi++)
                #pragma unroll
                for (int ni = 0; ni < 4; ni++) {
                    int nj = ni >> 1, p = (ni & 1) * 2;
                    mma16816(acc[mi][ni], af[mi], bh[nj][p], bh[nj][p + 1]);
                    mma16816(acc[mi][ni], af[mi], bl[nj][p], bl[nj][p + 1]);
                }
            // A-lo frags (reuse regs), lh MMAs
            #pragma unroll
            for (int mi = 0; mi < 4; mi++)
                ldsm_x4(af[mi], aBase + (uint32_t)(SPLIT_SZ << 1)
                                + (uint32_t)((mi * 16 * PITCH_A + ks * 16) << 1));
            #pragma unroll
            for (int mi = 0; mi < 4; mi++)
                #pragma unroll
                for (int ni = 0; ni < 4; ni++) {
                    int nj = ni >> 1, p = (ni & 1) * 2;
                    mma16816(acc[mi][ni], af[mi], bh[nj][p], bh[nj][p + 1]);
                }
        }
        __syncthreads();
    }

    // ---- epilogue ----
    const int rql = lane >> 2;          // 0..7
    const int cql = (lane & 3) << 1;    // 0,2,4,6
    #pragma unroll
    for (int mi = 0; mi < 4; mi++) {
        #pragma unroll
        for (int ni = 0; ni < 4; ni++) {
            int coln = nwarp + ni * 8 + cql;
            float b0 = 0.f, b1 = 0.f;
            if (HASBIAS) { b0 = sbias[coln]; b1 = sbias[coln + 1]; }
            #pragma unroll
            for (int half = 0; half < 2; half++) {
                size_t row = out_row0 + mwarp + mi * 16 + rql + half * 8;
                float v0 = acc[mi][ni][half * 2 + 0] + b0;
                float v1 = acc[mi][ni][half * 2 + 1] + b1;
                if (RELU) { v0 = fmaxf(v0, 0.f); v1 = fmaxf(v1, 0.f); }
                size_t goff = row * (size_t)Ncol + bn + coln;
                if (RESID) {
                    float2 r = *(const float2*)(resid + goff);
                    v0 += r.x; v1 += r.y;
                }
                if (OUTF32) *(float2*)(Cf + goff) = make_float2(v0, v1);
                if (OUTPLANES) {
                    uint16_t h0, l0, h1, l1;
                    split_bf16(v0, h0, l0);
                    split_bf16(v1, h1, l1);
                    *(uint32_t*)(Ch + goff) = (uint32_t)h0 | ((uint32_t)h1 << 16);
                    *(uint32_t*)(Cl + goff) = (uint32_t)l0 | ((uint32_t)l1 << 16);
                }
            }
        }
    }
}

// ---------------------------------------------------------------------------
// pooled[b][d] = mean_n x[b][n][d]
// ---------------------------------------------------------------------------
__global__ void pool_mean(const float* __restrict__ x, float* __restrict__ pooled)
{
    int idx = blockIdx.x * blockDim.x + threadIdx.x;
    int b = idx / Dn;
    int d = idx - b * Dn;
    const float* p = x + (size_t)b * Nn * Dn + d;
    float s = 0.f;
    #pragma unroll 8
    for (int n = 0; n < Nn; n++) s += p[(size_t)n * Dn];
    pooled[idx] = s * (1.f / Nn);
}

// ---------------------------------------------------------------------------
extern "C" void kernel_launch(void* const* d_in, const int* in_sizes, int n_in,
                              void* d_out, int out_size)
{
    const float* x0  = (const float*)d_in[0];
    const float* adj = (const float*)d_in[1];
    const float* W1  = (const float*)d_in[2];
    const float* b1  = (const float*)d_in[3];
    const float* W2  = (const float*)d_in[4];
    const float* b2  = (const float*)d_in[5];

    float* out      = (float*)d_out;
    float* out_x    = out;
    float* out_pool = out + (size_t)Bn * Nn * Dn;
    float* out_adj  = out_pool + (size_t)Bn * Dn;

    __nv_bfloat16 *adjh, *adjl, *xh, *xl, *nbh, *nbl, *hh, *hl,
                  *w1h, *w1l, *w2h, *w2l;
    float* gx;
    cudaGetSymbolAddress((void**)&adjh, g_adjh);
    cudaGetSymbolAddress((void**)&adjl, g_adjl);
    cudaGetSymbolAddress((void**)&xh,   g_xh);
    cudaGetSymbolAddress((void**)&xl,   g_xl);
    cudaGetSymbolAddress((void**)&nbh,  g_nbh);
    cudaGetSymbolAddress((void**)&nbl,  g_nbl);
    cudaGetSymbolAddress((void**)&hh,   g_hh);
    cudaGetSymbolAddress((void**)&hl,   g_hl);
    cudaGetSymbolAddress((void**)&w1h,  g_w1h);
    cudaGetSymbolAddress((void**)&w1l,  g_w1l);
    cudaGetSymbolAddress((void**)&w2h,  g_w2h);
    cudaGetSymbolAddress((void**)&w2l,  g_w2l);
    cudaGetSymbolAddress((void**)&gx,   g_x);

    softmax_rows<<<Nn, Nn>>>(adj, out_adj, adjh, adjl);
    split_convert<<<(Ln * Hn * Dn / 4 + 255) / 256, 256>>>(W1, w1h, w1l, Ln * Hn * Dn / 4);
    split_convert<<<(Ln * Dn * Hn / 4 + 255) / 256, 256>>>(W2, w2h, w2l, Ln * Dn * Hn / 4);
    split_convert<<<((int)((size_t)Bn * Nn * Dn / 4) + 255) / 256, 256>>>(
        x0, xh, xl, (int)((size_t)Bn * Nn * Dn / 4));

    const float* xin_f = x0;   // fp32 copy of current x (for residual)
    for (int i = 0; i < Ln; i++) {
        float* xout = (i == Ln - 1) ? out_x : gx;
        bool last = (i == Ln - 1);

        // neighbor = adj_norm @ x  (A=adj planes m x k; B=x planes [k][n], T case)
        mma_gemm<true, false, false, false, false, true>
            <<<dim3(Dn / 128, Nn / 128, Bn), 256>>>(
            adjh, adjl, xh, xl, nullptr, nullptr,
            nullptr, nbh, nbl, Dn, Nn);

        // h = relu(neighbor @ W1^T + b1)
        mma_gemm<false, true, true, false, false, true>
            <<<dim3(Hn / 128, (Bn * Nn) / 128, 1), 256>>>(
            nbh, nbl, w1h + (size_t)i * Hn * Dn, w1l + (size_t)i * Hn * Dn,
            b1 + (size_t)i * Hn, nullptr, nullptr, hh, hl, Hn, Dn);

        // x = x + h @ W2^T + b2  (fp32 out; also planes for next layer)
        if (!last)
            mma_gemm<false, true, false, true, true, true>
                <<<dim3(Dn / 128, (Bn * Nn) / 128, 1), 256>>>(
                hh, hl, w2h + (size_t)i * Dn * Hn, w2l + (size_t)i * Dn * Hn,
                b2 + (size_t)i * Dn, xin_f, xout, xh, xl, Dn, Hn);
        else
            mma_gemm<false, true, false, true, true, false>
                <<<dim3(Dn / 128, (Bn * Nn) / 128, 1), 256>>>(
                hh, hl, w2h + (size_t)i * Dn * Hn, w2l + (size_t)i * Dn * Hn,
                b2 + (size_t)i * Dn, xin_f, xout, nullptr, nullptr, Dn, Hn);

        xin_f = xout;
    }

    pool_mean<<<(Bn * Dn) / 256, 256>>>(out_x, out_pool);
}

// round 4
// speedup vs baseline: 2.8455x; 1.1331x over previous
#include <cuda_runtime.h>
#include <cuda_bf16.h>
#include <cstdint>

#define Bn 128
#define Nn 256
#define Dn 512
#define Hn 1024
#define Ln 3

// ---------------------------------------------------------------------------
// Scratch planes (static device arrays; 16B-aligned for uint4 access)
// ---------------------------------------------------------------------------
__device__ __align__(256) __nv_bfloat16 g_adjh[Nn * Nn];
__device__ __align__(256) __nv_bfloat16 g_adjl[Nn * Nn];
__device__ __align__(256) __nv_bfloat16 g_xh [(size_t)Bn * Nn * Dn];
__device__ __align__(256) __nv_bfloat16 g_xl [(size_t)Bn * Nn * Dn];
__device__ __align__(256) __nv_bfloat16 g_nbh[(size_t)Bn * Nn * Dn];
__device__ __align__(256) __nv_bfloat16 g_nbl[(size_t)Bn * Nn * Dn];
__device__ __align__(256) __nv_bfloat16 g_hh [(size_t)Bn * Nn * Hn];
__device__ __align__(256) __nv_bfloat16 g_hl [(size_t)Bn * Nn * Hn];
__device__ __align__(256) __nv_bfloat16 g_w1h[(size_t)Ln * Hn * Dn];
__device__ __align__(256) __nv_bfloat16 g_w1l[(size_t)Ln * Hn * Dn];
__device__ __align__(256) __nv_bfloat16 g_w2h[(size_t)Ln * Dn * Hn];
__device__ __align__(256) __nv_bfloat16 g_w2l[(size_t)Ln * Dn * Hn];
__device__ __align__(256) float         g_x  [(size_t)Bn * Nn * Dn];

// ---------------------------------------------------------------------------
// PTX helpers (sm_80-level: compiles at compute_103 target)
// ---------------------------------------------------------------------------
__device__ __forceinline__ uint32_t smem_u32(const void* p) {
    uint32_t a;
    asm("{ .reg .u64 t; cvta.to.shared.u64 t, %1; cvt.u32.u64 %0, t; }"
        : "=r"(a) : "l"(p));
    return a;
}
__device__ __forceinline__ void cp16(uint32_t s, const void* g) {
    asm volatile("cp.async.cg.shared.global [%0], [%1], 16;" :: "r"(s), "l"(g));
}
__device__ __forceinline__ void cp_commit() {
    asm volatile("cp.async.commit_group;" ::: "memory");
}
template<int N>
__device__ __forceinline__ void cp_wait() {
    asm volatile("cp.async.wait_group %0;" :: "n"(N) : "memory");
}
__device__ __forceinline__ void ldsm_x4(uint32_t (&r)[4], uint32_t addr) {
    asm volatile("ldmatrix.sync.aligned.m8n8.x4.shared.b16 {%0,%1,%2,%3}, [%4];"
        : "=r"(r[0]), "=r"(r[1]), "=r"(r[2]), "=r"(r[3]) : "r"(addr));
}
__device__ __forceinline__ void ldsm_x4_t(uint32_t (&r)[4], uint32_t addr) {
    asm volatile("ldmatrix.sync.aligned.m8n8.x4.trans.shared.b16 {%0,%1,%2,%3}, [%4];"
        : "=r"(r[0]), "=r"(r[1]), "=r"(r[2]), "=r"(r[3]) : "r"(addr));
}
__device__ __forceinline__ void mma16816(float (&d)[4], const uint32_t (&a)[4],
                                         uint32_t b0, uint32_t b1) {
    asm volatile(
        "mma.sync.aligned.m16n8k16.row.col.f32.bf16.bf16.f32 "
        "{%0,%1,%2,%3}, {%4,%5,%6,%7}, {%8,%9}, {%0,%1,%2,%3};"
        : "+f"(d[0]), "+f"(d[1]), "+f"(d[2]), "+f"(d[3])
        : "r"(a[0]), "r"(a[1]), "r"(a[2]), "r"(a[3]), "r"(b0), "r"(b1));
}
__device__ __forceinline__ void split_bf16(float v, uint16_t& h, uint16_t& l) {
    __nv_bfloat16 hb = __float2bfloat16(v);
    float hf = __bfloat162float(hb);
    __nv_bfloat16 lb = __float2bfloat16(v - hf);
    h = __bfloat16_as_ushort(hb);
    l = __bfloat16_as_ushort(lb);
}

// ---------------------------------------------------------------------------
// Row softmax over adjacency [N,N]: fp32 output + bf16 hi/lo planes
// ---------------------------------------------------------------------------
__global__ void softmax_rows(const float* __restrict__ adj,
                             float* __restrict__ out_adj,
                             __nv_bfloat16* __restrict__ hi,
                             __nv_bfloat16* __restrict__ lo)
{
    int row = blockIdx.x;
    int t   = threadIdx.x;
    float v = adj[row * Nn + t];

    __shared__ float red[8];
    float m = v;
    #pragma unroll
    for (int o = 16; o > 0; o >>= 1)
        m = fmaxf(m, __shfl_xor_sync(0xffffffffu, m, o));
    if ((t & 31) == 0) red[t >> 5] = m;
    __syncthreads();
    m = red[0];
    #pragma unroll
    for (int i = 1; i < 8; i++) m = fmaxf(m, red[i]);
    __syncthreads();

    float e = expf(v - m);
    float s = e;
    #pragma unroll
    for (int o = 16; o > 0; o >>= 1)
        s += __shfl_xor_sync(0xffffffffu, s, o);
    if ((t & 31) == 0) red[t >> 5] = s;
    __syncthreads();
    s = red[0];
    #pragma unroll
    for (int i = 1; i < 8; i++) s += red[i];

    float o = e / s;
    out_adj[row * Nn + t] = o;
    uint16_t h, l;
    split_bf16(o, h, l);
    hi[row * Nn + t] = __ushort_as_bfloat16(h);
    lo[row * Nn + t] = __ushort_as_bfloat16(l);
}

// ---------------------------------------------------------------------------
// fp32 -> (bf16 hi, bf16 lo) planes
// ---------------------------------------------------------------------------
__global__ void split_convert(const float* __restrict__ in,
                              __nv_bfloat16* __restrict__ hi,
                              __nv_bfloat16* __restrict__ lo, int n4)
{
    int idx = blockIdx.x * blockDim.x + threadIdx.x;
    if (idx >= n4) return;
    float4 v = ((const float4*)in)[idx];
    float a[4] = {v.x, v.y, v.z, v.w};
    uint16_t h[4], l[4];
    #pragma unroll
    for (int e = 0; e < 4; e++) split_bf16(a[e], h[e], l[e]);
    ((uint2*)hi)[idx] = make_uint2((uint32_t)h[0] | ((uint32_t)h[1] << 16),
                                   (uint32_t)h[2] | ((uint32_t)h[3] << 16));
    ((uint2*)lo)[idx] = make_uint2((uint32_t)l[0] | ((uint32_t)l[1] << 16),
                                   (uint32_t)l[2] | ((uint32_t)l[3] << 16));
}

// ---------------------------------------------------------------------------
// mma.sync GEMM with cp.async 2-stage double buffering.
//   A: hi/lo bf16 planes, [M,K] row-major
//   B NT: hi/lo planes [Ncol,K] row-major (weights)
//   B T : hi/lo planes [K,Ncol] row-major (x; batched via blockIdx.z)
// CTA tile 128x128x32, 8 warps (2x4), warp tile 64x32, 3-MMA split precision.
// ---------------------------------------------------------------------------
#define PITCH_A  40      // halves; 80B rows (16B multiple)
#define PITCH_BT 136     // halves; 272B rows (16B multiple)
#define SPLIT_SZ 5120    // halves per split plane (A / B-NT)
#define SPLIT_BT 4352    // halves per split plane (B-T: 32*136)
#define STAGE_B  40960   // bytes per stage: A 20480 + B 20480
#define DSMEM_B  (2 * STAGE_B)

template<bool TRANSB, bool HASBIAS, bool RELU, bool RESID, bool OUTF32, bool OUTPLANES>
__global__ void __launch_bounds__(256, 2)
mma_gemm(const __nv_bfloat16* __restrict__ Ah, const __nv_bfloat16* __restrict__ Al,
         const __nv_bfloat16* __restrict__ Bh, const __nv_bfloat16* __restrict__ Bl,
         const float* __restrict__ bias, const float* __restrict__ resid,
         float* __restrict__ Cf,
         __nv_bfloat16* __restrict__ Ch, __nv_bfloat16* __restrict__ Cl,
         int Ncol, int K)
{
    extern __shared__ __align__(16) char dsm[];
    __shared__ float sbias[128];

    const int tid  = threadIdx.x;
    const int lane = tid & 31;
    const int wid  = tid >> 5;
    const int mwarp = (wid >> 2) * 64;
    const int nwarp = (wid & 3) * 32;
    const int bm = blockIdx.y * 128;
    const int bn = blockIdx.x * 128;
    const int z  = blockIdx.z;

    const size_t arow0 = (size_t)bm;
    const __nv_bfloat16* Bhp = Bh;
    const __nv_bfloat16* Blp = Bl;
    size_t out_row0;
    if (TRANSB) {
        Bhp = Bh + (size_t)z * Nn * Dn;
        Blp = Bl + (size_t)z * Nn * Dn;
        out_row0 = (size_t)z * Nn + bm;
    } else {
        out_row0 = (size_t)bm;
    }

    if (HASBIAS && tid < 128) sbias[tid] = bias[bn + tid];

    float acc[4][4][4];
    #pragma unroll
    for (int mi = 0; mi < 4; mi++)
        #pragma unroll
        for (int ni = 0; ni < 4; ni++)
            #pragma unroll
            for (int e = 0; e < 4; e++) acc[mi][ni][e] = 0.f;

    const uint32_t dsm_u = smem_u32(dsm);

    // ---- per-thread cp.async target offsets (byte offsets within a stage) ----
    // A: f in [0,512): r = f>>2 (row 0..127), c = (f&3)<<3 (k col 0,8,16,24)
    const int fa0 = tid, fa1 = tid + 256;
    const uint32_t aOff0 = (uint32_t)(((fa0 >> 2) * PITCH_A + ((fa0 & 3) << 3)) << 1);
    const uint32_t aOff1 = (uint32_t)(((fa1 >> 2) * PITCH_A + ((fa1 & 3) << 3)) << 1);
    uint32_t bOff0, bOff1;
    if (TRANSB) {
        bOff0 = (uint32_t)(((fa0 >> 4) * PITCH_BT + ((fa0 & 15) << 3)) << 1);
        bOff1 = (uint32_t)(((fa1 >> 4) * PITCH_BT + ((fa1 & 15) << 3)) << 1);
    } else {
        bOff0 = aOff0;
        bOff1 = aOff1;
    }

    // ---- per-thread ldmatrix base offsets (byte, within a stage) ----
    const int q = lane >> 3, li = lane & 7;
    const uint32_t aLds = (uint32_t)(((mwarp + (q & 1) * 8 + li) * PITCH_A
                                     + (q >> 1) * 8) << 1);
    uint32_t bLds;
    if (TRANSB)
        bLds = (uint32_t)((((q & 1) * 8 + li) * PITCH_BT
                          + nwarp + (q >> 1) * 8) << 1);
    else
        bLds = (uint32_t)(((nwarp + (q >> 1) * 8 + li) * PITCH_A
                          + (q & 1) * 8) << 1);
    const uint32_t bSplitOff = (uint32_t)((TRANSB ? SPLIT_BT : SPLIT_SZ) << 1);

    // ---- issue loads for one chunk into stage s ----
    auto issue = [&](int k0, int s) {
        const uint32_t sa = dsm_u + (uint32_t)s * STAGE_B;
        const uint32_t sb = sa + 20480u;
        // A hi/lo
        {
            int r0 = fa0 >> 2, c0 = (fa0 & 3) << 3;
            int r1 = fa1 >> 2, c1 = (fa1 & 3) << 3;
            size_t g0 = (arow0 + r0) * (size_t)K + k0 + c0;
            size_t g1 = (arow0 + r1) * (size_t)K + k0 + c1;
            cp16(sa + aOff0, Ah + g0);
            cp16(sa + aOff1, Ah + g1);
            cp16(sa + (uint32_t)(SPLIT_SZ << 1) + aOff0, Al + g0);
            cp16(sa + (uint32_t)(SPLIT_SZ << 1) + aOff1, Al + g1);
        }
        // B hi/lo
        if (TRANSB) {
            int r0 = fa0 >> 4, c0 = (fa0 & 15) << 3;
            int r1 = fa1 >> 4, c1 = (fa1 & 15) << 3;
            size_t g0 = (size_t)(k0 + r0) * Ncol + bn + c0;
            size_t g1 = (size_t)(k0 + r1) * Ncol + bn + c1;
            cp16(sb + bOff0, Bhp + g0);
            cp16(sb + bOff1, Bhp + g1);
            cp16(sb + bSplitOff + bOff0, Blp + g0);
            cp16(sb + bSplitOff + bOff1, Blp + g1);
        } else {
            int r0 = fa0 >> 2, c0 = (fa0 & 3) << 3;
            int r1 = fa1 >> 2, c1 = (fa1 & 3) << 3;
            size_t g0 = (size_t)(bn + r0) * K + k0 + c0;
            size_t g1 = (size_t)(bn + r1) * K + k0 + c1;
            cp16(sb + bOff0, Bhp + g0);
            cp16(sb + bOff1, Bhp + g1);
            cp16(sb + bSplitOff + bOff0, Blp + g0);
            cp16(sb + bSplitOff + bOff1, Blp + g1);
        }
        cp_commit();
    };

    const int nchunks = K >> 5;
    issue(0, 0);

    for (int ch = 0; ch < nchunks; ch++) {
        if (ch + 1 < nchunks) {
            issue((ch + 1) << 5, (ch + 1) & 1);
            cp_wait<1>();
        } else {
            cp_wait<0>();
        }
        __syncthreads();

        const uint32_t sa = dsm_u + (uint32_t)(ch & 1) * STAGE_B + aLds;
        const uint32_t sb = dsm_u + (uint32_t)(ch & 1) * STAGE_B + 20480u + bLds;

        #pragma unroll
        for (int ks = 0; ks < 2; ks++) {
            uint32_t bh[2][4], bl[2][4];
            #pragma unroll
            for (int nj = 0; nj < 2; nj++) {
                if (TRANSB) {
                    uint32_t o = (uint32_t)((ks * 16 * PITCH_BT + nj * 16) << 1);
                    ldsm_x4_t(bh[nj], sb + o);
                    ldsm_x4_t(bl[nj], sb + bSplitOff + o);
                } else {
                    uint32_t o = (uint32_t)((nj * 16 * PITCH_A + ks * 16) << 1);
                    ldsm_x4(bh[nj], sb + o);
                    ldsm_x4(bl[nj], sb + bSplitOff + o);
                }
            }
            uint32_t af[4][4];
            #pragma unroll
            for (int mi = 0; mi < 4; mi++)
                ldsm_x4(af[mi], sa + (uint32_t)((mi * 16 * PITCH_A + ks * 16) << 1));
            #pragma unroll
            for (int mi = 0; mi < 4; mi++)
                #pragma unroll
                for (int ni = 0; ni < 4; ni++) {
                    int nj = ni >> 1, p = (ni & 1) * 2;
                    mma16816(acc[mi][ni], af[mi], bh[nj][p], bh[nj][p + 1]);
                    mma16816(acc[mi][ni], af[mi], bl[nj][p], bl[nj][p + 1]);
                }
            #pragma unroll
            for (int mi = 0; mi < 4; mi++)
                ldsm_x4(af[mi], sa + (uint32_t)(SPLIT_SZ << 1)
                                + (uint32_t)((mi * 16 * PITCH_A + ks * 16) << 1));
            #pragma unroll
            for (int mi = 0; mi < 4; mi++)
                #pragma unroll
                for (int ni = 0; ni < 4; ni++) {
                    int nj = ni >> 1, p = (ni & 1) * 2;
                    mma16816(acc[mi][ni], af[mi], bh[nj][p], bh[nj][p + 1]);
                }
        }
        __syncthreads();
    }

    // ---- epilogue ----
    const int rql = lane >> 2;
    const int cql = (lane & 3) << 1;
    #pragma unroll
    for (int mi = 0; mi < 4; mi++) {
        #pragma unroll
        for (int ni = 0; ni < 4; ni++) {
            int coln = nwarp + ni * 8 + cql;
            float b0 = 0.f, b1 = 0.f;
            if (HASBIAS) { b0 = sbias[coln]; b1 = sbias[coln + 1]; }
            #pragma unroll
            for (int half = 0; half < 2; half++) {
                size_t row = out_row0 + mwarp + mi * 16 + rql + half * 8;
                float v0 = acc[mi][ni][half * 2 + 0] + b0;
                float v1 = acc[mi][ni][half * 2 + 1] + b1;
                if (RELU) { v0 = fmaxf(v0, 0.f); v1 = fmaxf(v1, 0.f); }
                size_t goff = row * (size_t)Ncol + bn + coln;
                if (RESID) {
                    float2 r = *(const float2*)(resid + goff);
                    v0 += r.x; v1 += r.y;
                }
                if (OUTF32) *(float2*)(Cf + goff) = make_float2(v0, v1);
                if (OUTPLANES) {
                    uint16_t h0, l0, h1, l1;
                    split_bf16(v0, h0, l0);
                    split_bf16(v1, h1, l1);
                    *(uint32_t*)(Ch + goff) = (uint32_t)h0 | ((uint32_t)h1 << 16);
                    *(uint32_t*)(Cl + goff) = (uint32_t)l0 | ((uint32_t)l1 << 16);
                }
            }
        }
    }
}

// ---------------------------------------------------------------------------
__global__ void pool_mean(const float* __restrict__ x, float* __restrict__ pooled)
{
    int idx = blockIdx.x * blockDim.x + threadIdx.x;
    int b = idx / Dn;
    int d = idx - b * Dn;
    const float* p = x + (size_t)b * Nn * Dn + d;
    float s = 0.f;
    #pragma unroll 8
    for (int n = 0; n < Nn; n++) s += p[(size_t)n * Dn];
    pooled[idx] = s * (1.f / Nn);
}

// ---------------------------------------------------------------------------
extern "C" void kernel_launch(void* const* d_in, const int* in_sizes, int n_in,
                              void* d_out, int out_size)
{
    const float* x0  = (const float*)d_in[0];
    const float* adj = (const float*)d_in[1];
    const float* W1  = (const float*)d_in[2];
    const float* b1  = (const float*)d_in[3];
    const float* W2  = (const float*)d_in[4];
    const float* b2  = (const float*)d_in[5];

    float* out      = (float*)d_out;
    float* out_x    = out;
    float* out_pool = out + (size_t)Bn * Nn * Dn;
    float* out_adj  = out_pool + (size_t)Bn * Dn;

    __nv_bfloat16 *adjh, *adjl, *xh, *xl, *nbh, *nbl, *hh, *hl,
                  *w1h, *w1l, *w2h, *w2l;
    float* gx;
    cudaGetSymbolAddress((void**)&adjh, g_adjh);
    cudaGetSymbolAddress((void**)&adjl, g_adjl);
    cudaGetSymbolAddress((void**)&xh,   g_xh);
    cudaGetSymbolAddress((void**)&xl,   g_xl);
    cudaGetSymbolAddress((void**)&nbh,  g_nbh);
    cudaGetSymbolAddress((void**)&nbl,  g_nbl);
    cudaGetSymbolAddress((void**)&hh,   g_hh);
    cudaGetSymbolAddress((void**)&hl,   g_hl);
    cudaGetSymbolAddress((void**)&w1h,  g_w1h);
    cudaGetSymbolAddress((void**)&w1l,  g_w1l);
    cudaGetSymbolAddress((void**)&w2h,  g_w2h);
    cudaGetSymbolAddress((void**)&w2l,  g_w2l);
    cudaGetSymbolAddress((void**)&gx,   g_x);

    cudaFuncSetAttribute(mma_gemm<true,  false, false, false, false, true>,
        cudaFuncAttributeMaxDynamicSharedMemorySize, DSMEM_B);
    cudaFuncSetAttribute(mma_gemm<false, true,  true,  false, false, true>,
        cudaFuncAttributeMaxDynamicSharedMemorySize, DSMEM_B);
    cudaFuncSetAttribute(mma_gemm<false, true,  false, true,  true,  true>,
        cudaFuncAttributeMaxDynamicSharedMemorySize, DSMEM_B);
    cudaFuncSetAttribute(mma_gemm<false, true,  false, true,  true,  false>,
        cudaFuncAttributeMaxDynamicSharedMemorySize, DSMEM_B);

    softmax_rows<<<Nn, Nn>>>(adj, out_adj, adjh, adjl);
    split_convert<<<(Ln * Hn * Dn / 4 + 255) / 256, 256>>>(W1, w1h, w1l, Ln * Hn * Dn / 4);
    split_convert<<<(Ln * Dn * Hn / 4 + 255) / 256, 256>>>(W2, w2h, w2l, Ln * Dn * Hn / 4);
    split_convert<<<((int)((size_t)Bn * Nn * Dn / 4) + 255) / 256, 256>>>(
        x0, xh, xl, (int)((size_t)Bn * Nn * Dn / 4));

    const float* xin_f = x0;
    for (int i = 0; i < Ln; i++) {
        float* xout = (i == Ln - 1) ? out_x : gx;
        bool last = (i == Ln - 1);

        // neighbor = adj_norm @ x
        mma_gemm<true, false, false, false, false, true>
            <<<dim3(Dn / 128, Nn / 128, Bn), 256, DSMEM_B>>>(
            adjh, adjl, xh, xl, nullptr, nullptr,
            nullptr, nbh, nbl, Dn, Nn);

        // h = relu(neighbor @ W1^T + b1)
        mma_gemm<false, true, true, false, false, true>
            <<<dim3(Hn / 128, (Bn * Nn) / 128, 1), 256, DSMEM_B>>>(
            nbh, nbl, w1h + (size_t)i * Hn * Dn, w1l + (size_t)i * Hn * Dn,
            b1 + (size_t)i * Hn, nullptr, nullptr, hh, hl, Hn, Dn);

        // x = x + h @ W2^T + b2
        if (!last)
            mma_gemm<false, true, false, true, true, true>
                <<<dim3(Dn / 128, (Bn * Nn) / 128, 1), 256, DSMEM_B>>>(
                hh, hl, w2h + (size_t)i * Dn * Hn, w2l + (size_t)i * Dn * Hn,
                b2 + (size_t)i * Dn, xin_f, xout, xh, xl, Dn, Hn);
        else
            mma_gemm<false, true, false, true, true, false>
                <<<dim3(Dn / 128, (Bn * Nn) / 128, 1), 256, DSMEM_B>>>(
                hh, hl, w2h + (size_t)i * Dn * Hn, w2l + (size_t)i * Dn * Hn,
                b2 + (size_t)i * Dn, xin_f, xout, nullptr, nullptr, Dn, Hn);

        xin_f = xout;
    }

    pool_mean<<<(Bn * Dn) / 256, 256>>>(out_x, out_pool);
}